// round 13
// baseline (speedup 1.0000x reference)
#include <cuda_runtime.h>
#include <cuda_fp16.h>
#include <math.h>
#include <stdint.h>

// ---------------- problem constants ----------------
#define Bn    32
#define Hs    56
#define Ws_   56
#define Cc    192
#define WS    7
#define SS    3
#define NH    6
#define Nn    49
#define HD    32
#define BW    2048
#define ROWS  100352
#define HID   768
#define SCALE 0.17677669529663687f
#define LNEPS 1e-5f

// ---------------- helpers ----------------
__device__ __forceinline__ uint32_t smem_u32(const void* p) {
    uint32_t a;
    asm("{ .reg .u64 t; cvta.to.shared.u64 t, %1; cvt.u32.u64 %0, t; }" : "=r"(a) : "l"(p));
    return a;
}

#define LDSM4(r, a) \
    asm volatile("ldmatrix.sync.aligned.m8n8.x4.shared.b16 {%0,%1,%2,%3}, [%4];" \
        : "=r"((r)[0]), "=r"((r)[1]), "=r"((r)[2]), "=r"((r)[3]) : "r"(a))

#define MMA16816(d, a, b0, b1) \
    asm volatile("mma.sync.aligned.m16n8k16.row.col.f32.f16.f16.f32 " \
        "{%0,%1,%2,%3}, {%4,%5,%6,%7}, {%8,%9}, {%0,%1,%2,%3};" \
        : "+f"((d)[0]), "+f"((d)[1]), "+f"((d)[2]), "+f"((d)[3]) \
        : "r"((a)[0]), "r"((a)[1]), "r"((a)[2]), "r"((a)[3]), "r"(b0), "r"(b1))

// ---------------- scratch ----------------
__device__ __half g_xw[(size_t)ROWS * Cc];
__device__ __half g_qkv[(size_t)ROWS * 3 * Cc];
__device__ __half g_ao[(size_t)ROWS * Cc];
__device__ float  g_h[(size_t)ROWS * Cc];
__device__ __half g_hid[(size_t)ROWS * HID];
__device__ __half g_wq[3 * Cc * Cc];
__device__ __half g_wp[Cc * Cc];
__device__ __half g_f1[HID * Cc];
__device__ __half g_f2[Cc * HID];

// ---------------- weight convert (single fp16) ----------------
__global__ void convert_kernel(const float* __restrict__ w,
                               __half* __restrict__ o, int n) {
    int i = blockIdx.x * 256 + threadIdx.x;
    if (i < n) o[i] = __float2half(w[i]);
}

// ---------------- LN kernels (write fp16) ----------------
__global__ void ln1_gather_kernel(const float* __restrict__ x,
                                  const float* __restrict__ g, const float* __restrict__ b,
                                  __half* __restrict__ o) {
    int r = blockIdx.x * 8 + (threadIdx.x >> 5);
    if (r >= ROWS) return;
    int lane = threadIdx.x & 31;
    int b_ = r / Nn, t = r - b_ * Nn;
    int bb = b_ >> 6, w = b_ & 63;
    int hr = (w >> 3) * WS + t / WS;
    int wr = (w & 7) * WS + t % WS;
    int sh = hr + SS; if (sh >= Hs) sh -= Hs;
    int sw = wr + SS; if (sw >= Ws_) sw -= Ws_;
    const float* src = x + ((size_t)(bb * Hs * Ws_ + sh * Ws_ + sw)) * Cc;
    float v[6], s = 0.f, s2 = 0.f;
    #pragma unroll
    for (int j = 0; j < 6; j++) { v[j] = src[lane + 32 * j]; s += v[j]; s2 += v[j] * v[j]; }
    #pragma unroll
    for (int o2 = 16; o2; o2 >>= 1) { s += __shfl_xor_sync(~0u, s, o2); s2 += __shfl_xor_sync(~0u, s2, o2); }
    float mu = s * (1.f / Cc), var = s2 * (1.f / Cc) - mu * mu;
    float rs = rsqrtf(var + LNEPS);
    size_t d0 = (size_t)r * Cc;
    #pragma unroll
    for (int j = 0; j < 6; j++) {
        int c = lane + 32 * j;
        o[d0 + c] = __float2half((v[j] - mu) * rs * g[c] + b[c]);
    }
}

__global__ void ln_plain_kernel(const float* __restrict__ x,
                                const float* __restrict__ g, const float* __restrict__ b,
                                __half* __restrict__ o) {
    int r = blockIdx.x * 8 + (threadIdx.x >> 5);
    if (r >= ROWS) return;
    int lane = threadIdx.x & 31;
    const float* src = x + (size_t)r * Cc;
    float v[6], s = 0.f, s2 = 0.f;
    #pragma unroll
    for (int j = 0; j < 6; j++) { v[j] = src[lane + 32 * j]; s += v[j]; s2 += v[j] * v[j]; }
    #pragma unroll
    for (int o2 = 16; o2; o2 >>= 1) { s += __shfl_xor_sync(~0u, s, o2); s2 += __shfl_xor_sync(~0u, s2, o2); }
    float mu = s * (1.f / Cc), var = s2 * (1.f / Cc) - mu * mu;
    float rs = rsqrtf(var + LNEPS);
    size_t d0 = (size_t)r * Cc;
    #pragma unroll
    for (int j = 0; j < 6; j++) {
        int c = lane + 32 * j;
        o[d0 + c] = __float2half((v[j] - mu) * rs * g[c] + b[c]);
    }
}

// ---------------- mma.sync fp16 GEMM (R8-proven: BK=32) ----------
// Block tile 128x64, 8 warps: warp grid 4(m) x 2(n), warp tile 32x32.
// EPI 0: +bias -> fp16 Oh        (qkv)
// EPI 1: +bias, GELU -> fp16 Oh  (fc1)
// EPI 2: +bias, scatter + resid -> fp32 Co (proj)
// EPI 3: +bias, +resid -> fp32 Co (fc2)
#define BKt   32
#define ASTR  40                       // 32 + 8 pad (half elems)
#define OFF_A  0
#define OFF_B  10240
#define BUF_SZ 15360
#define SMEM_TOT (BUF_SZ * 2)          // 30720

template <int N_, int K_, int EPI>
__global__ __launch_bounds__(256) void gemm_mma(
    const __half* __restrict__ A, const __half* __restrict__ Wh,
    const float* __restrict__ bias, float* __restrict__ Co,
    const float* __restrict__ resid, __half* __restrict__ Oh) {
    extern __shared__ char smem[];
    const int t = threadIdx.x, lane = t & 31, wid = t >> 5;
    const int wm = wid & 3, wn = wid >> 2;
    const int m0 = blockIdx.y * 128, n0 = blockIdx.x * 64;
    constexpr int NKT = K_ / BKt;

    float acc[2][4][4];
    #pragma unroll
    for (int i = 0; i < 2; i++)
        #pragma unroll
        for (int j = 0; j < 4; j++)
            #pragma unroll
            for (int k = 0; k < 4; k++) acc[i][j][k] = 0.f;

    const int arow = t >> 2, akq = t & 3;
    {
        #pragma unroll
        for (int l = 0; l < 2; l++) {
            int row = arow + l * 64;
            uint32_t so = (uint32_t)row * (ASTR * 2) + akq * 16;
            *(uint4*)(smem + OFF_A + so) = *(const uint4*)(A + (size_t)(m0 + row) * K_ + akq * 8);
        }
        uint32_t so = (uint32_t)arow * (ASTR * 2) + akq * 16;
        *(uint4*)(smem + OFF_B + so) = *(const uint4*)(Wh + (size_t)(n0 + arow) * K_ + akq * 8);
    }
    __syncthreads();

    const int fr = lane & 15;
    const int fc = (lane >> 4) * 8;

    for (int kt = 0; kt < NKT; kt++) {
        char* buf = smem + (kt & 1) * BUF_SZ;
        uint4 pa[2], pb;
        if (kt + 1 < NKT) {
            int k0n = (kt + 1) * BKt;
            #pragma unroll
            for (int l = 0; l < 2; l++) {
                int row = arow + l * 64;
                pa[l] = *(const uint4*)(A + (size_t)(m0 + row) * K_ + k0n + akq * 8);
            }
            pb = *(const uint4*)(Wh + (size_t)(n0 + arow) * K_ + k0n + akq * 8);
        }

        const uint32_t sA = smem_u32(buf + OFF_A);
        const uint32_t sB = smem_u32(buf + OFF_B);

        #pragma unroll
        for (int ks = 0; ks < 2; ks++) {
            int col = ks * 16 + fc;
            uint32_t ah[2][4], bh[2][4];
            #pragma unroll
            for (int mf = 0; mf < 2; mf++) {
                uint32_t off = (uint32_t)(wm * 32 + mf * 16 + fr) * (ASTR * 2) + col * 2;
                LDSM4(ah[mf], sA + off);
            }
            #pragma unroll
            for (int nf2 = 0; nf2 < 2; nf2++) {
                uint32_t off = (uint32_t)(wn * 32 + nf2 * 16 + fr) * (ASTR * 2) + col * 2;
                LDSM4(bh[nf2], sB + off);
            }
            #pragma unroll
            for (int mf = 0; mf < 2; mf++)
                #pragma unroll
                for (int nf = 0; nf < 4; nf++) {
                    int n2 = nf >> 1, sel = nf & 1;
                    MMA16816(acc[mf][nf], ah[mf], bh[n2][sel], bh[n2][sel + 2]);
                }
        }

        if (kt + 1 < NKT) {
            char* nb = smem + ((kt + 1) & 1) * BUF_SZ;
            #pragma unroll
            for (int l = 0; l < 2; l++) {
                int row = arow + l * 64;
                uint32_t so = (uint32_t)row * (ASTR * 2) + akq * 16;
                *(uint4*)(nb + OFF_A + so) = pa[l];
            }
            uint32_t so = (uint32_t)arow * (ASTR * 2) + akq * 16;
            *(uint4*)(nb + OFF_B + so) = pb;
            __syncthreads();
        }
    }

    const int r_in = lane >> 2, c_in = (lane & 3) * 2;
    #pragma unroll
    for (int mf = 0; mf < 2; mf++) {
        #pragma unroll
        for (int rr = 0; rr < 2; rr++) {
            int m = m0 + wm * 32 + mf * 16 + r_in + rr * 8;
            size_t dbase;
            if (EPI == 2) {
                int b_ = m / Nn, tok = m - b_ * Nn;
                int bb = b_ >> 6, w = b_ & 63;
                int hr = (w >> 3) * WS + tok / WS;
                int wr = (w & 7) * WS + tok % WS;
                int dh = hr + SS; if (dh >= Hs) dh -= Hs;
                int dw = wr + SS; if (dw >= Ws_) dw -= Ws_;
                dbase = ((size_t)(bb * Hs * Ws_ + dh * Ws_ + dw)) * Cc;
            } else {
                dbase = (size_t)m * N_;
            }
            #pragma unroll
            for (int nf = 0; nf < 4; nf++) {
                int col = n0 + wn * 32 + nf * 8 + c_in;
                float2 bv = *(const float2*)(bias + col);
                float v0 = acc[mf][nf][rr * 2]     + bv.x;
                float v1 = acc[mf][nf][rr * 2 + 1] + bv.y;
                if (EPI == 0) {
                    __half2 hh;
                    hh.x = __float2half(v0); hh.y = __float2half(v1);
                    *(__half2*)(Oh + dbase + col) = hh;
                } else if (EPI == 1) {
                    v0 = 0.5f * v0 * (1.f + erff(v0 * 0.7071067811865476f));
                    v1 = 0.5f * v1 * (1.f + erff(v1 * 0.7071067811865476f));
                    __half2 hh;
                    hh.x = __float2half(v0); hh.y = __float2half(v1);
                    *(__half2*)(Oh + dbase + col) = hh;
                } else {
                    float2 xr = *(const float2*)(resid + dbase + col);
                    *(float2*)(Co + dbase + col) = make_float2(v0 + xr.x, v1 + xr.y);
                }
            }
        }
    }
}

// ---------------- fused attention: fp16 qkv in, broadcast k/v ----------
#define SSTR 51
__global__ __launch_bounds__(64) void attn_kernel(
    const __half* __restrict__ qkv, const float* __restrict__ rpb,
    __half* __restrict__ oh) {
    int blk = blockIdx.x;
    int head = blk % NH;
    int b_ = blk / NH;
    int w = b_ & 63;
    int wh = w >> 3, ww = w & 7;

    __shared__ float ks[Nn * HD];
    __shared__ float vs[Nn * HD];
    __shared__ float ss[Nn * SSTR];
    __shared__ float biasv[169];
    __shared__ int grp[Nn];

    int t = threadIdx.x;
    for (int idx = t; idx < Nn * 8; idx += 64) {
        int row = idx >> 3, d4 = idx & 7;
        const __half* base = qkv + ((size_t)(b_ * Nn + row)) * (3 * Cc) + head * HD + d4 * 4;
        __half2 k0 = *(const __half2*)(base + Cc);
        __half2 k1 = *(const __half2*)(base + Cc + 2);
        __half2 v0 = *(const __half2*)(base + 2 * Cc);
        __half2 v1 = *(const __half2*)(base + 2 * Cc + 2);
        float2 kf0 = __half22float2(k0), kf1 = __half22float2(k1);
        float2 vf0 = __half22float2(v0), vf1 = __half22float2(v1);
        *(float4*)(ks + row * HD + d4 * 4) = make_float4(kf0.x, kf0.y, kf1.x, kf1.y);
        *(float4*)(vs + row * HD + d4 * 4) = make_float4(vf0.x, vf0.y, vf1.x, vf1.y);
    }
    for (int i = t; i < 169; i += 64) biasv[i] = rpb[i * NH + head];
    if (t < Nn) {
        int hr = wh * WS + t / WS, wr = ww * WS + t % WS;
        int rh = hr < 49 ? 0 : (hr < 53 ? 1 : 2);
        int rw = wr < 49 ? 0 : (wr < 53 ? 1 : 2);
        grp[t] = rh * 3 + rw;
    }
    __syncthreads();

    const int i = t;
    const bool act = (i < Nn);
    int ri = 0, ci = 0, gi = 0;
    if (act) { ri = i / WS; ci = i - ri * WS; gi = grp[i]; }

    float4 qv[8];
    if (act) {
        const __half* qsrc = qkv + ((size_t)(b_ * Nn + i)) * (3 * Cc) + head * HD;
        #pragma unroll
        for (int d4 = 0; d4 < 8; d4++) {
            __half2 q0 = *(const __half2*)(qsrc + d4 * 4);
            __half2 q1 = *(const __half2*)(qsrc + d4 * 4 + 2);
            float2 f0 = __half22float2(q0), f1 = __half22float2(q1);
            qv[d4] = make_float4(f0.x * SCALE, f0.y * SCALE, f1.x * SCALE, f1.y * SCALE);
        }
    }

    #pragma unroll 7
    for (int j = 0; j < Nn; j++) {
        const float4* kj = (const float4*)(ks + j * HD);
        float acc = 0.f;
        #pragma unroll
        for (int d4 = 0; d4 < 8; d4++) {
            float4 kk = kj[d4];
            acc += qv[d4].x * kk.x + qv[d4].y * kk.y + qv[d4].z * kk.z + qv[d4].w * kk.w;
        }
        if (act) {
            int rj = j / WS, cj = j - rj * WS;
            float bias = biasv[(ri - rj + 6) * 13 + (ci - cj + 6)];
            float msk = (gi != grp[j]) ? -100.f : 0.f;
            ss[i * SSTR + j] = acc + bias + msk;
        }
    }

    float inv = 0.f;
    if (act) {
        float mx = -1e30f;
        #pragma unroll 7
        for (int j = 0; j < Nn; j++) mx = fmaxf(mx, ss[i * SSTR + j]);
        float sm = 0.f;
        #pragma unroll 7
        for (int j = 0; j < Nn; j++) {
            float e = __expf(ss[i * SSTR + j] - mx);
            ss[i * SSTR + j] = e;
            sm += e;
        }
        inv = 1.f / sm;
    }

    float4 acc[8];
    #pragma unroll
    for (int d4 = 0; d4 < 8; d4++) acc[d4] = make_float4(0.f, 0.f, 0.f, 0.f);
    #pragma unroll 7
    for (int j = 0; j < Nn; j++) {
        const float4* vj = (const float4*)(vs + j * HD);
        float p = act ? ss[i * SSTR + j] : 0.f;
        #pragma unroll
        for (int d4 = 0; d4 < 8; d4++) {
            float4 vv = vj[d4];
            acc[d4].x = fmaf(p, vv.x, acc[d4].x);
            acc[d4].y = fmaf(p, vv.y, acc[d4].y);
            acc[d4].z = fmaf(p, vv.z, acc[d4].z);
            acc[d4].w = fmaf(p, vv.w, acc[d4].w);
        }
    }

    if (act) {
        size_t base = ((size_t)(b_ * Nn + i)) * Cc + head * HD;
        #pragma unroll
        for (int d4 = 0; d4 < 8; d4++) {
            float4 o = acc[d4];
            __half2 h0, h1;
            h0.x = __float2half(o.x * inv); h0.y = __float2half(o.y * inv);
            h1.x = __float2half(o.z * inv); h1.y = __float2half(o.w * inv);
            *(__half2*)(oh + base + d4 * 4)     = h0;
            *(__half2*)(oh + base + d4 * 4 + 2) = h1;
        }
    }
}

// ---------------- launch ----------------
extern "C" void kernel_launch(void* const* d_in, const int* in_sizes, int n_in,
                              void* d_out, int out_size) {
    const float* x       = (const float*)d_in[0];
    const float* norm1_g = (const float*)d_in[1];
    const float* norm1_b = (const float*)d_in[2];
    const float* qkv_w   = (const float*)d_in[3];
    const float* qkv_b   = (const float*)d_in[4];
    const float* proj_w  = (const float*)d_in[5];
    const float* proj_b  = (const float*)d_in[6];
    const float* rpb     = (const float*)d_in[7];
    const float* norm2_g = (const float*)d_in[8];
    const float* norm2_b = (const float*)d_in[9];
    const float* fc1_w   = (const float*)d_in[10];
    const float* fc1_b   = (const float*)d_in[11];
    const float* fc2_w   = (const float*)d_in[12];
    const float* fc2_b   = (const float*)d_in[13];
    float* out = (float*)d_out;

    __half *xw, *qkv, *ao, *hid, *wq, *wp, *f1, *f2;
    float *h;
    cudaGetSymbolAddress((void**)&xw, g_xw);
    cudaGetSymbolAddress((void**)&qkv, g_qkv);
    cudaGetSymbolAddress((void**)&ao, g_ao);
    cudaGetSymbolAddress((void**)&h,  g_h);
    cudaGetSymbolAddress((void**)&hid, g_hid);
    cudaGetSymbolAddress((void**)&wq, g_wq);
    cudaGetSymbolAddress((void**)&wp, g_wp);
    cudaGetSymbolAddress((void**)&f1, g_f1);
    cudaGetSymbolAddress((void**)&f2, g_f2);

    cudaFuncSetAttribute(gemm_mma<3 * Cc, Cc, 0>, cudaFuncAttributeMaxDynamicSharedMemorySize, SMEM_TOT);
    cudaFuncSetAttribute(gemm_mma<Cc, Cc, 2>,     cudaFuncAttributeMaxDynamicSharedMemorySize, SMEM_TOT);
    cudaFuncSetAttribute(gemm_mma<HID, Cc, 1>,    cudaFuncAttributeMaxDynamicSharedMemorySize, SMEM_TOT);
    cudaFuncSetAttribute(gemm_mma<Cc, HID, 3>,    cudaFuncAttributeMaxDynamicSharedMemorySize, SMEM_TOT);

    convert_kernel<<<(3 * Cc * Cc + 255) / 256, 256>>>(qkv_w, wq, 3 * Cc * Cc);
    convert_kernel<<<(Cc * Cc + 255) / 256, 256>>>(proj_w, wp, Cc * Cc);
    convert_kernel<<<(HID * Cc + 255) / 256, 256>>>(fc1_w, f1, HID * Cc);
    convert_kernel<<<(Cc * HID + 255) / 256, 256>>>(fc2_w, f2, Cc * HID);

    ln1_gather_kernel<<<ROWS / 8, 256>>>(x, norm1_g, norm1_b, xw);

    gemm_mma<3 * Cc, Cc, 0><<<dim3(9, ROWS / 128), 256, SMEM_TOT>>>(
        xw, wq, qkv_b, nullptr, nullptr, qkv);

    attn_kernel<<<BW * NH, 64>>>(qkv, rpb, ao);

    gemm_mma<Cc, Cc, 2><<<dim3(3, ROWS / 128), 256, SMEM_TOT>>>(
        ao, wp, proj_b, h, x, nullptr);

    ln_plain_kernel<<<ROWS / 8, 256>>>(h, norm2_g, norm2_b, xw);

    gemm_mma<HID, Cc, 1><<<dim3(12, ROWS / 128), 256, SMEM_TOT>>>(
        xw, f1, fc1_b, nullptr, nullptr, hid);

    gemm_mma<Cc, HID, 3><<<dim3(3, ROWS / 128), 256, SMEM_TOT>>>(
        hid, f2, fc2_b, out, h, nullptr);
}